// round 3
// baseline (speedup 1.0000x reference)
#include <cuda_runtime.h>
#include <cuda_bf16.h>

// ============================================================================
// RelationAwareAttention — GB300 sm_103a
//
// Shapes: bs=8, h=8, L=512, d=64, P=1024.
// Identities:
//   bias[i][j]   = q_i . r_k[path_map[i,j]]            -> gather from dense q@r_k^T
//   out_rv[i][:] = sum_j p[i][j] * r_v[path_map[i,j]]  -> smem scatter + dense GEMM
//
// One block = one (b,h) x 16-query tile. All phases fused in one kernel.
// r_k / K tiles are staged gmem->smem via double-buffered cp.async (coalesced),
// all hot GEMM loops use packed fma.rn.f32x2 (2x fp32 throughput).
//
// path_map dtype is sniffed on-device (JAX x64-off may demote int64->int32).
// ============================================================================

#define BSZ   8
#define NH    8
#define LQ    512
#define DH    64
#define PN    1024
#define TQ    16
#define NT    256
#define NTILE (LQ / TQ)

#define STR   66                 // padded floats per staged row (2-way conflicts max)
#define STG_F (128 * STR)        // floats per stage buffer (128 rows)

typedef unsigned long long ull;

static __device__ float g_scratch[BSZ * NH * LQ * LQ]; // fallback output buffer

__device__ __forceinline__ ull pack2(float lo, float hi) {
    ull r; asm("mov.b64 %0, {%1, %2};" : "=l"(r) : "f"(lo), "f"(hi)); return r;
}
__device__ __forceinline__ float2 unpack2(ull v) {
    float2 r; asm("mov.b64 {%0, %1}, %2;" : "=f"(r.x), "=f"(r.y) : "l"(v)); return r;
}
__device__ __forceinline__ void fma2(ull& d, ull a, ull b) {
    asm("fma.rn.f32x2 %0, %1, %2, %0;" : "+l"(d) : "l"(a), "l"(b));
}
__device__ __forceinline__ float unpack_sum(ull v) {
    float2 f = unpack2(v); return f.x + f.y;
}

__device__ __forceinline__ void cp_commit() {
    asm volatile("cp.async.commit_group;");
}
__device__ __forceinline__ void cp_wait0() {
    asm volatile("cp.async.wait_group 0;");
}
__device__ __forceinline__ void cp_wait1() {
    asm volatile("cp.async.wait_group 1;");
}

// Copy one 128x64 f32 tile (row stride 64 in gmem) into a padded stage buffer.
// Each warp copies 16 rows; each row = 32 lanes x 8B = 256B, fully coalesced.
__device__ __forceinline__ void stage_load(const float* __restrict__ src_rows,
                                           float* dstbuf, int tid) {
    #pragma unroll
    for (int u = 0; u < 16; u++) {
        int e  = tid + u * NT;
        int r  = e >> 5;
        int c2 = (e & 31) * 2;
        unsigned dst = (unsigned)__cvta_generic_to_shared(dstbuf + r * STR + c2);
        const float* src = src_rows + (size_t)r * DH + c2;
        asm volatile("cp.async.ca.shared.global [%0], [%1], 8;" :: "r"(dst), "l"(src));
    }
    cp_commit();
}

// Shared memory layout (dynamic):
//   [0,      4096)    q_t2 : ull[32][16]    q tile, k-pairs x i (transposed)
//   [4096,  69632)    bias : f32[16][1024]  (later reused as scat)
//   [69632, 102400)   sc   : f32[16][512]   scores -> p_attn
//   [102400,118784)   idxs : u16[16][512]   (later reused as red f32[4][1024])
//   [118784,186368)   stg  : 2 x 128 x STR f32 (cp.async double buffer)
#define SMEM_BYTES (4096 + 65536 + 32768 + 16384 + 2 * STG_F * 4)

__global__ void __launch_bounds__(NT, 1)
ra_attn_kernel(const float* __restrict__ q,  const float* __restrict__ k,
               const float* __restrict__ v,  const float* __restrict__ rk,
               const float* __restrict__ rv, const void* __restrict__ pm_raw,
               const int* __restrict__ mask,
               float* attn_out, float* p_out)
{
    if (attn_out == nullptr) attn_out = g_scratch;
    if (p_out    == nullptr) p_out    = g_scratch;

    extern __shared__ char smem_raw[];
    ull*            q_t2 = (ull*)smem_raw;
    float*          bias = (float*)(smem_raw + 4096);
    float*          sc   = (float*)(smem_raw + 4096 + 65536);
    unsigned short* idxs = (unsigned short*)(smem_raw + 4096 + 65536 + 32768);
    float*          red  = (float*)idxs;
    float*          stg  = (float*)(smem_raw + 4096 + 65536 + 32768 + 16384);

    const int bh     = blockIdx.x >> 5;
    const int tile   = blockIdx.x & 31;
    const int b      = bh >> 3;
    const int i_base = tile * TQ;
    const int tid    = threadIdx.x;

    const float*     qg  = q  + (size_t)bh * LQ * DH;
    const float*     kg  = k  + (size_t)bh * LQ * DH;
    const float*     vg  = v  + (size_t)bh * LQ * DH;
    const float*     rkg = rk + (size_t)bh * PN * DH;
    const float*     rvg = rv + (size_t)bh * PN * DH;
    const int*       mg  = mask + (size_t)b * LQ * LQ;

    // ---- path_map dtype sniff (int64 vs int32) ----------------------------
    // Legal values are [0, PN]. If the buffer is really int32, an int64 view
    // of the first 8 entries combines two random values and exceeds PN with
    // overwhelming probability. Same addresses for all blocks: deterministic.
    const long long* pm64 = (const long long*)pm_raw;
    const int*       pm32 = (const int*)pm_raw;
    bool is64 = true;
    #pragma unroll
    for (int t = 0; t < 8; t++) {
        long long vv = pm64[t];
        if (vv < 0 || vv > PN) is64 = false;
    }
    const size_t pm_base = (size_t)b * LQ * LQ;

    // ---- phase 0: load q tile, transposed into k-pairs --------------------
    for (int e = tid; e < TQ * 32; e += NT) {
        int i = e >> 5, k2 = e & 31;
        float2 qv = *(const float2*)(qg + (size_t)(i_base + i) * DH + k2 * 2);
        q_t2[k2 * 16 + i] = pack2(qv.x, qv.y);
    }

    // thread -> (row-in-stage, i-half) mapping shared by phases 1 and 2
    const int p_loc = tid & 127;
    const int ih    = (tid >> 7) * 8;     // 0 or 8
    __syncthreads();

    // ---- phase 1: bias[16][1024] = q_tile @ r_k^T (8 staged 128-row tiles)
    stage_load(rkg, stg, tid);
    #pragma unroll 1
    for (int s = 0; s < 8; s++) {
        if (s < 7) stage_load(rkg + (size_t)(s + 1) * 128 * DH, stg + ((s + 1) & 1) * STG_F, tid);
        if (s < 7) cp_wait1(); else cp_wait0();
        __syncthreads();

        const float* B = stg + (s & 1) * STG_F + p_loc * STR;
        ull acc[8];
        #pragma unroll
        for (int ii = 0; ii < 8; ii++) acc[ii] = 0ULL;

        #pragma unroll 8
        for (int k2 = 0; k2 < 32; k2++) {
            const ulonglong2* qp = (const ulonglong2*)(q_t2 + k2 * 16 + ih);
            ulonglong2 q01 = qp[0], q23 = qp[1], q45 = qp[2], q67 = qp[3];
            ull rkv = *(const ull*)(B + k2 * 2);
            fma2(acc[0], rkv, q01.x); fma2(acc[1], rkv, q01.y);
            fma2(acc[2], rkv, q23.x); fma2(acc[3], rkv, q23.y);
            fma2(acc[4], rkv, q45.x); fma2(acc[5], rkv, q45.y);
            fma2(acc[6], rkv, q67.x); fma2(acc[7], rkv, q67.y);
        }
        int p = s * 128 + p_loc;
        #pragma unroll
        for (int ii = 0; ii < 8; ii++) bias[(ih + ii) * PN + p] = unpack_sum(acc[ii]);
        __syncthreads();   // compute done before next prefetch overwrites this buffer
    }

    // ---- phase 2: scores[16][512] = q@K^T + gather(bias), scale, mask -----
    stage_load(kg, stg, tid);
    #pragma unroll 1
    for (int s = 0; s < 4; s++) {
        if (s < 3) stage_load(kg + (size_t)(s + 1) * 128 * DH, stg + ((s + 1) & 1) * STG_F, tid);
        if (s < 3) cp_wait1(); else cp_wait0();
        __syncthreads();

        const float* B = stg + (s & 1) * STG_F + p_loc * STR;
        ull acc[8];
        #pragma unroll
        for (int ii = 0; ii < 8; ii++) acc[ii] = 0ULL;

        #pragma unroll 8
        for (int k2 = 0; k2 < 32; k2++) {
            const ulonglong2* qp = (const ulonglong2*)(q_t2 + k2 * 16 + ih);
            ulonglong2 q01 = qp[0], q23 = qp[1], q45 = qp[2], q67 = qp[3];
            ull kv = *(const ull*)(B + k2 * 2);
            fma2(acc[0], kv, q01.x); fma2(acc[1], kv, q01.y);
            fma2(acc[2], kv, q23.x); fma2(acc[3], kv, q23.y);
            fma2(acc[4], kv, q45.x); fma2(acc[5], kv, q45.y);
            fma2(acc[6], kv, q67.x); fma2(acc[7], kv, q67.y);
        }
        int j = s * 128 + p_loc;
        #pragma unroll
        for (int ii = 0; ii < 8; ii++) {
            int   i   = ih + ii;
            int   ig  = i_base + i;
            float sv  = unpack_sum(acc[ii]);
            size_t ofs = pm_base + (size_t)ig * LQ + j;
            int   idx = is64 ? (int)pm64[ofs] : pm32[ofs];
            if (idx < PN) sv += bias[i * PN + idx];
            sv *= 0.125f;                        // 1/sqrt(64*SQRT_NORM)
            if (mg[(size_t)ig * LQ + j] == 0) sv = -1e9f;
            sc[i * LQ + j]   = sv;
            idxs[i * LQ + j] = (unsigned short)idx;
        }
        __syncthreads();
    }

    // ---- phase 3: row softmax + write p_attn ------------------------------
    {
        int warp = tid >> 5, lane = tid & 31;
        for (int r = warp; r < TQ; r += 8) {
            float* row = sc + r * LQ;
            float  m   = -1e30f;
            for (int jj = lane; jj < LQ; jj += 32) m = fmaxf(m, row[jj]);
            #pragma unroll
            for (int o = 16; o; o >>= 1) m = fmaxf(m, __shfl_xor_sync(0xffffffffu, m, o));
            float ssum = 0.f;
            for (int jj = lane; jj < LQ; jj += 32) {
                float e = __expf(row[jj] - m);
                row[jj] = e;
                ssum += e;
            }
            #pragma unroll
            for (int o = 16; o; o >>= 1) ssum += __shfl_xor_sync(0xffffffffu, ssum, o);
            float inv = 1.0f / ssum;
            float* pg = p_out + ((size_t)bh * LQ + (i_base + r)) * LQ;
            for (int jj = lane; jj < LQ; jj += 32) {
                float pv = row[jj] * inv;
                row[jj]  = pv;
                pg[jj]   = pv;
            }
        }
    }
    __syncthreads();

    // ---- phase 4: scat[16][1024] (reuse bias smem) ------------------------
    float* scat = bias;
    for (int e = tid; e < TQ * PN; e += NT) scat[e] = 0.f;
    __syncthreads();
    {
        int i  = tid & 15;
        int j0 = (tid >> 4) * 32;
        const unsigned short* irow = idxs + i * LQ;
        const float*          prow = sc + i * LQ;
        float*                srow = scat + i * PN;
        #pragma unroll 4
        for (int jj = 0; jj < 32; jj++) {
            int j   = j0 + jj;
            int idx = irow[j];
            if (idx < PN) atomicAdd(&srow[idx], prow[j]);
        }
    }
    __syncthreads();

    // ---- phase 5: out[16][64] = p@V + scat@r_v ----------------------------
    // 64 output tiles of 4i x 4d; 4 j-split groups, smem reduction.
    {
        int t64 = tid & 63, g = tid >> 6;
        int i0  = (t64 >> 4) * 4;
        int d0  = (t64 & 15) * 4;
        ull acc[4][2];
        #pragma unroll
        for (int ii = 0; ii < 4; ii++) { acc[ii][0] = 0ULL; acc[ii][1] = 0ULL; }

        #pragma unroll 4
        for (int j = g * 128; j < g * 128 + 128; j++) {
            float4 vv = *(const float4*)(vg + (size_t)j * DH + d0);
            ull v01 = pack2(vv.x, vv.y), v23 = pack2(vv.z, vv.w);
            #pragma unroll
            for (int ii = 0; ii < 4; ii++) {
                float w  = sc[(i0 + ii) * LQ + j];
                ull   w2 = pack2(w, w);
                fma2(acc[ii][0], w2, v01);
                fma2(acc[ii][1], w2, v23);
            }
        }
        #pragma unroll 4
        for (int j = g * 256; j < g * 256 + 256; j++) {
            float4 vv = *(const float4*)(rvg + (size_t)j * DH + d0);
            ull v01 = pack2(vv.x, vv.y), v23 = pack2(vv.z, vv.w);
            #pragma unroll
            for (int ii = 0; ii < 4; ii++) {
                float w  = scat[(i0 + ii) * PN + j];
                ull   w2 = pack2(w, w);
                fma2(acc[ii][0], w2, v01);
                fma2(acc[ii][1], w2, v23);
            }
        }
        __syncthreads();   // idxs region dead -> red is safe to write
        #pragma unroll
        for (int ii = 0; ii < 4; ii++) {
            float2 lo = unpack2(acc[ii][0]);
            float2 hi = unpack2(acc[ii][1]);
            float* rp = red + g * 1024 + (i0 + ii) * 64 + d0;
            rp[0] = lo.x; rp[1] = lo.y; rp[2] = hi.x; rp[3] = hi.y;
        }
    }
    __syncthreads();
    {
        int e = tid * 4;
        float4 o;
        o.x = red[e + 0] + red[1024 + e + 0] + red[2048 + e + 0] + red[3072 + e + 0];
        o.y = red[e + 1] + red[1024 + e + 1] + red[2048 + e + 1] + red[3072 + e + 1];
        o.z = red[e + 2] + red[1024 + e + 2] + red[2048 + e + 2] + red[3072 + e + 2];
        o.w = red[e + 3] + red[1024 + e + 3] + red[2048 + e + 3] + red[3072 + e + 3];
        int i = e >> 6, d = e & 63;
        *(float4*)(attn_out + ((size_t)bh * LQ + i_base + i) * DH + d) = o;
    }
}

extern "C" void kernel_launch(void* const* d_in, const int* in_sizes, int n_in,
                              void* d_out, int out_size) {
    const float* q    = (const float*)d_in[0];
    const float* kk   = (const float*)d_in[1];
    const float* v    = (const float*)d_in[2];
    const float* rk   = (const float*)d_in[3];
    const float* rv   = (const float*)d_in[4];
    const void*  pm   = d_in[5];
    const int*   mask = (const int*)d_in[6];

    const long long ATT = (long long)BSZ * NH * LQ * DH;  //  2,097,152
    const long long PAT = (long long)BSZ * NH * LQ * LQ;  // 16,777,216

    float* out = (float*)d_out;
    float* attn_out;
    float* p_out;
    if ((long long)out_size >= ATT + PAT) {        // tuple concat: (attn_sum, p_attn)
        attn_out = out;
        p_out    = out + ATT;
    } else if ((long long)out_size == PAT) {       // p_attn only
        attn_out = nullptr;                        // kernel redirects to g_scratch
        p_out    = out;
    } else {                                       // attn_sum only
        attn_out = out;
        p_out    = nullptr;
    }

    cudaFuncSetAttribute(ra_attn_kernel,
                         cudaFuncAttributeMaxDynamicSharedMemorySize, SMEM_BYTES);
    ra_attn_kernel<<<BSZ * NH * NTILE, NT, SMEM_BYTES>>>(
        q, kk, v, rk, rv, pm, mask, attn_out, p_out);
}

// round 9
// speedup vs baseline: 1.0621x; 1.0621x over previous
#include <cuda_runtime.h>
#include <cuda_bf16.h>

// ============================================================================
// RelationAwareAttention — GB300 sm_103a
//
// Shapes: bs=8, h=8, L=512, d=64, P=1024.
// Identities:
//   bias[i][j]   = q_i . r_k[path_map[i,j]]            -> gather from dense q@r_k^T
//   out_rv[i][:] = sum_j p[i][j] * r_v[path_map[i,j]]  -> smem scatter + dense GEMM
//
// One block = one (b,h) x 8-query tile, 256 threads, 91KB smem -> 2 CTAs/SM
// (R3 ncu: occ 12.5%, issue 18% -> latency-bound; cross-CTA overlap hides
// barrier/phase-transition serialization that a single fat CTA cannot).
// r_k / K staged via double-buffered cp.async (64-row tiles); GEMMs use
// packed fma.rn.f32x2. path_map dtype sniffed on-device (JAX x64-off).
// ============================================================================

#define BSZ   8
#define NH    8
#define LQ    512
#define DH    64
#define PN    1024
#define TQ    8
#define NT    256
#define NTILE (LQ / TQ)          // 64 tiles per (b,h)

#define SROWS 64                 // staged rows per buffer
#define STR   66                 // padded floats per staged row (2-way conflicts max)
#define STG_F (SROWS * STR)      // floats per stage buffer

typedef unsigned long long ull;

static __device__ float g_scratch[BSZ * NH * LQ * LQ]; // fallback output buffer

__device__ __forceinline__ ull pack2(float lo, float hi) {
    ull r; asm("mov.b64 %0, {%1, %2};" : "=l"(r) : "f"(lo), "f"(hi)); return r;
}
__device__ __forceinline__ float2 unpack2(ull v) {
    float2 r; asm("mov.b64 {%0, %1}, %2;" : "=f"(r.x), "=f"(r.y) : "l"(v)); return r;
}
__device__ __forceinline__ void fma2(ull& d, ull a, ull b) {
    asm("fma.rn.f32x2 %0, %1, %2, %0;" : "+l"(d) : "l"(a), "l"(b));
}
__device__ __forceinline__ float unpack_sum(ull v) {
    float2 f = unpack2(v); return f.x + f.y;
}

__device__ __forceinline__ void cp_commit() { asm volatile("cp.async.commit_group;"); }
__device__ __forceinline__ void cp_wait0()  { asm volatile("cp.async.wait_group 0;"); }
__device__ __forceinline__ void cp_wait1()  { asm volatile("cp.async.wait_group 1;"); }

// Copy one 64x64 f32 tile (row stride 64 in gmem) into a padded stage buffer.
// 2048 8-byte elements; 256 threads x 8 iters; gmem side fully coalesced.
__device__ __forceinline__ void stage_load(const float* __restrict__ src_rows,
                                           float* dstbuf, int tid) {
    #pragma unroll
    for (int u = 0; u < 8; u++) {
        int e  = tid + u * NT;
        int r  = e >> 5;
        int c2 = (e & 31) * 2;
        unsigned dst = (unsigned)__cvta_generic_to_shared(dstbuf + r * STR + c2);
        const float* src = src_rows + (size_t)r * DH + c2;
        asm volatile("cp.async.ca.shared.global [%0], [%1], 8;" :: "r"(dst), "l"(src));
    }
    cp_commit();
}

// Shared memory layout (dynamic), total 93184 B (~91KB) -> 2 CTAs/SM:
//   [0,     2048)   q_t2 : ull[32][8]     q tile, k-pairs x i (transposed)
//   [2048, 34816)   bias : f32[8][1024]   (later reused as scat)
//   [34816,51200)   sc   : f32[8][512]    scores -> p_attn
//   [51200,59392)   idxs : u16[8][512]    (later reused as red f32[4][512])
//   [59392,93184)   stg  : 2 x 64 x STR f32 (cp.async double buffer)
#define OFF_BIAS 2048
#define OFF_SC   (OFF_BIAS + 32768)
#define OFF_IDX  (OFF_SC + 16384)
#define OFF_STG  (OFF_IDX + 8192)
#define SMEM_BYTES (OFF_STG + 2 * STG_F * 4)

__global__ void __launch_bounds__(NT, 2)
ra_attn_kernel(const float* __restrict__ q,  const float* __restrict__ k,
               const float* __restrict__ v,  const float* __restrict__ rk,
               const float* __restrict__ rv, const void* __restrict__ pm_raw,
               const int* __restrict__ mask,
               float* attn_out, float* p_out)
{
    if (attn_out == nullptr) attn_out = g_scratch;
    if (p_out    == nullptr) p_out    = g_scratch;

    extern __shared__ char smem_raw[];
    ull*            q_t2 = (ull*)smem_raw;
    float*          bias = (float*)(smem_raw + OFF_BIAS);
    float*          sc   = (float*)(smem_raw + OFF_SC);
    unsigned short* idxs = (unsigned short*)(smem_raw + OFF_IDX);
    float*          red  = (float*)idxs;
    float*          stg  = (float*)(smem_raw + OFF_STG);

    const int bh     = blockIdx.x >> 6;          // 64 tiles per bh
    const int tile   = blockIdx.x & 63;
    const int b      = bh >> 3;
    const int i_base = tile * TQ;
    const int tid    = threadIdx.x;

    const float* qg  = q  + (size_t)bh * LQ * DH;
    const float* kg  = k  + (size_t)bh * LQ * DH;
    const float* vg  = v  + (size_t)bh * LQ * DH;
    const float* rkg = rk + (size_t)bh * PN * DH;
    const float* rvg = rv + (size_t)bh * PN * DH;
    const int*   mg  = mask + (size_t)b * LQ * LQ;

    // ---- path_map dtype sniff (int64 vs int32) ----------------------------
    // Legal values lie in [0, PN]. If the buffer is really int32, the int64
    // view of the first entries exceeds PN with overwhelming probability.
    const long long* pm64 = (const long long*)pm_raw;
    const int*       pm32 = (const int*)pm_raw;
    bool is64 = true;
    #pragma unroll
    for (int t = 0; t < 8; t++) {
        long long vv = pm64[t];
        if (vv < 0 || vv > PN) is64 = false;
    }
    const size_t pm_base = (size_t)b * LQ * LQ;

    // ---- phase 0: load q tile, transposed into k-pairs --------------------
    {
        int i = tid >> 5, k2 = tid & 31;         // 256 = 8*32 exactly
        float2 qv = *(const float2*)(qg + (size_t)(i_base + i) * DH + k2 * 2);
        q_t2[k2 * TQ + i] = pack2(qv.x, qv.y);
    }

    // thread -> (row-in-stage, i-pair) mapping shared by phases 1 and 2
    const int p_loc = tid & 63;                  // 64 staged rows
    const int i2    = (tid >> 6) * 2;            // 0,2,4,6
    __syncthreads();

    // ---- phase 1: bias[8][1024] = q_tile @ r_k^T (16 staged 64-row tiles) -
    stage_load(rkg, stg, tid);
    #pragma unroll 1
    for (int s = 0; s < 16; s++) {
        if (s < 15) stage_load(rkg + (size_t)(s + 1) * SROWS * DH, stg + ((s + 1) & 1) * STG_F, tid);
        if (s < 15) cp_wait1(); else cp_wait0();
        __syncthreads();

        const float* B = stg + (s & 1) * STG_F + p_loc * STR;
        ull acc0 = 0ULL, acc1 = 0ULL;

        #pragma unroll 8
        for (int k2 = 0; k2 < 32; k2++) {
            ulonglong2 q01 = *(const ulonglong2*)(q_t2 + k2 * TQ + i2);  // warp-broadcast
            ull rkv = *(const ull*)(B + k2 * 2);
            fma2(acc0, rkv, q01.x);
            fma2(acc1, rkv, q01.y);
        }
        int p = s * SROWS + p_loc;
        bias[i2 * PN + p]       = unpack_sum(acc0);
        bias[(i2 + 1) * PN + p] = unpack_sum(acc1);
        __syncthreads();   // compute done before next prefetch overwrites buffer
    }

    // ---- phase 2: scores[8][512] = q@K^T + gather(bias), scale, mask ------
    stage_load(kg, stg, tid);
    #pragma unroll 1
    for (int s = 0; s < 8; s++) {
        if (s < 7) stage_load(kg + (size_t)(s + 1) * SROWS * DH, stg + ((s + 1) & 1) * STG_F, tid);

        // prefetch path indices + mask for this stage (overlaps the GEMM)
        int j = s * SROWS + p_loc;
        int idxr[2], mr[2];
        #pragma unroll
        for (int ii = 0; ii < 2; ii++) {
            int    ig  = i_base + i2 + ii;
            size_t ofs = pm_base + (size_t)ig * LQ + j;
            idxr[ii] = is64 ? (int)pm64[ofs] : pm32[ofs];
            mr[ii]   = mg[(size_t)ig * LQ + j];
        }

        if (s < 7) cp_wait1(); else cp_wait0();
        __syncthreads();

        const float* B = stg + (s & 1) * STG_F + p_loc * STR;
        ull acc0 = 0ULL, acc1 = 0ULL;

        #pragma unroll 8
        for (int k2 = 0; k2 < 32; k2++) {
            ulonglong2 q01 = *(const ulonglong2*)(q_t2 + k2 * TQ + i2);
            ull kv = *(const ull*)(B + k2 * 2);
            fma2(acc0, kv, q01.x);
            fma2(acc1, kv, q01.y);
        }
        #pragma unroll
        for (int ii = 0; ii < 2; ii++) {
            int   i   = i2 + ii;
            float sv  = unpack_sum(ii ? acc1 : acc0);
            int   idx = idxr[ii];
            if (idx < PN) sv += bias[i * PN + idx];
            sv *= 0.125f;                        // 1/sqrt(64*SQRT_NORM)
            if (mr[ii] == 0) sv = -1e9f;
            sc[i * LQ + j]   = sv;
            idxs[i * LQ + j] = (unsigned short)idx;
        }
        __syncthreads();
    }

    // ---- phase 3: row softmax + write p_attn (one warp per row, 8 warps) --
    {
        int warp = tid >> 5, lane = tid & 31;
        float* row = sc + warp * LQ;
        float  m   = -1e30f;
        #pragma unroll 4
        for (int jj = lane; jj < LQ; jj += 32) m = fmaxf(m, row[jj]);
        #pragma unroll
        for (int o = 16; o; o >>= 1) m = fmaxf(m, __shfl_xor_sync(0xffffffffu, m, o));
        float ssum = 0.f;
        #pragma unroll 4
        for (int jj = lane; jj < LQ; jj += 32) {
            float e = __expf(row[jj] - m);
            row[jj] = e;
            ssum += e;
        }
        #pragma unroll
        for (int o = 16; o; o >>= 1) ssum += __shfl_xor_sync(0xffffffffu, ssum, o);
        float inv = 1.0f / ssum;
        float* pg = p_out + ((size_t)bh * LQ + (i_base + warp)) * LQ;
        #pragma unroll 4
        for (int jj = lane; jj < LQ; jj += 32) {
            float pv = row[jj] * inv;
            row[jj]  = pv;
            pg[jj]   = pv;
        }
    }
    __syncthreads();

    // ---- phase 4: scat[8][1024] (reuse bias smem) -------------------------
    float* scat = bias;
    #pragma unroll 8
    for (int e = tid; e < TQ * PN; e += NT) scat[e] = 0.f;
    __syncthreads();
    {
        int i  = tid & 7;
        int j0 = (tid >> 3) * 16;                // 32 chunks of 16 j per row
        const unsigned short* irow = idxs + i * LQ;
        const float*          prow = sc + i * LQ;
        float*                srow = scat + i * PN;
        #pragma unroll 4
        for (int jj = 0; jj < 16; jj++) {
            int j   = j0 + jj;
            int idx = irow[j];
            if (idx < PN) atomicAdd(&srow[idx], prow[j]);
        }
    }
    __syncthreads();

    // ---- phase 5: out[8][64] = p@V + scat@r_v -----------------------------
    // 4 j-split groups of 64 threads; each thread: 2 i's x 4 d's.
    {
        int t64 = tid & 63, g = tid >> 6;
        int i0  = (t64 >> 4) * 2;                // 0,2,4,6
        int d0  = (t64 & 15) * 4;
        ull acc[2][2];
        acc[0][0] = acc[0][1] = acc[1][0] = acc[1][1] = 0ULL;

        #pragma unroll 4
        for (int j = g * 128; j < g * 128 + 128; j++) {
            float4 vv = *(const float4*)(vg + (size_t)j * DH + d0);
            ull v01 = pack2(vv.x, vv.y), v23 = pack2(vv.z, vv.w);
            #pragma unroll
            for (int ii = 0; ii < 2; ii++) {
                float w  = sc[(i0 + ii) * LQ + j];
                ull   w2 = pack2(w, w);
                fma2(acc[ii][0], w2, v01);
                fma2(acc[ii][1], w2, v23);
            }
        }
        #pragma unroll 4
        for (int j = g * 256; j < g * 256 + 256; j++) {
            float4 vv = *(const float4*)(rvg + (size_t)j * DH + d0);
            ull v01 = pack2(vv.x, vv.y), v23 = pack2(vv.z, vv.w);
            #pragma unroll
            for (int ii = 0; ii < 2; ii++) {
                float w  = scat[(i0 + ii) * PN + j];
                ull   w2 = pack2(w, w);
                fma2(acc[ii][0], w2, v01);
                fma2(acc[ii][1], w2, v23);
            }
        }
        __syncthreads();   // idxs region dead -> red is safe to write
        #pragma unroll
        for (int ii = 0; ii < 2; ii++) {
            float2 lo = unpack2(acc[ii][0]);
            float2 hi = unpack2(acc[ii][1]);
            float* rp = red + g * 512 + (i0 + ii) * 64 + d0;
            rp[0] = lo.x; rp[1] = lo.y; rp[2] = hi.x; rp[3] = hi.y;
        }
    }
    __syncthreads();
    if (tid < 128) {
        int e = tid * 4;                          // 512 outputs
        float4 o;
        o.x = red[e + 0] + red[512 + e + 0] + red[1024 + e + 0] + red[1536 + e + 0];
        o.y = red[e + 1] + red[512 + e + 1] + red[1024 + e + 1] + red[1536 + e + 1];
        o.z = red[e + 2] + red[512 + e + 2] + red[1024 + e + 2] + red[1536 + e + 2];
        o.w = red[e + 3] + red[512 + e + 3] + red[1024 + e + 3] + red[1536 + e + 3];
        int i = e >> 6, d = e & 63;
        *(float4*)(attn_out + ((size_t)bh * LQ + i_base + i) * DH + d) = o;
    }
}

extern "C" void kernel_launch(void* const* d_in, const int* in_sizes, int n_in,
                              void* d_out, int out_size) {
    const float* q    = (const float*)d_in[0];
    const float* kk   = (const float*)d_in[1];
    const float* v    = (const float*)d_in[2];
    const float* rk   = (const float*)d_in[3];
    const float* rv   = (const float*)d_in[4];
    const void*  pm   = d_in[5];
    const int*   mask = (const int*)d_in[6];

    const long long ATT = (long long)BSZ * NH * LQ * DH;  //  2,097,152
    const long long PAT = (long long)BSZ * NH * LQ * LQ;  // 16,777,216

    float* out = (float*)d_out;
    float* attn_out;
    float* p_out;
    if ((long long)out_size >= ATT + PAT) {        // tuple concat: (attn_sum, p_attn)
        attn_out = out;
        p_out    = out + ATT;
    } else if ((long long)out_size == PAT) {       // p_attn only
        attn_out = nullptr;
        p_out    = out;
    } else {                                       // attn_sum only
        attn_out = out;
        p_out    = nullptr;
    }

    cudaFuncSetAttribute(ra_attn_kernel,
                         cudaFuncAttributeMaxDynamicSharedMemorySize, SMEM_BYTES);
    ra_attn_kernel<<<BSZ * NH * NTILE, NT, SMEM_BYTES>>>(
        q, kk, v, rk, rv, pm, mask, attn_out, p_out);
}

// round 15
// speedup vs baseline: 1.6294x; 1.5341x over previous
#include <cuda_runtime.h>
#include <cuda_bf16.h>

// ============================================================================
// RelationAwareAttention — GB300 sm_103a
//
// Shapes: bs=8, h=8, L=512, d=64, P=1024.
// Identities:
//   bias[i][j]   = q_i . r_k[path_map[i,j]]            -> gather from dense q@r_k^T
//   out_rv[i][:] = sum_j p[i][j] * r_v[path_map[i,j]]  -> smem scatter + dense GEMM
//
// One block = one (b,h) x 8-query tile, 256 threads, 91KB smem -> 2 CTAs/SM.
// R9 ncu: L1=71.5% is the binding pipe -> this version cuts L1 wavefronts:
//  * phases 1-2: 128-row single-buffered stages, 4-i-deep threads
//    (4 wf / 4 fma2 per k2 instead of 3 wf / 2 fma2)
//  * phase 5: one warp per V/r_v row, 8-i register accs, packed-pair
//    sc2/scat2 operands (row read once; 3 wf/row instead of 8)
// ============================================================================

#define BSZ   8
#define NH    8
#define LQ    512
#define DH    64
#define PN    1024
#define TQ    8
#define NT    256
#define NTILE (LQ / TQ)          // 64 tiles per (b,h)

#define SROWS 128                // staged rows per (single) buffer
#define STR   66                 // padded floats per staged row (2-way conflicts max)
#define STG_F (SROWS * STR)      // floats per stage buffer

typedef unsigned long long ull;

static __device__ float g_scratch[BSZ * NH * LQ * LQ]; // fallback output buffer

__device__ __forceinline__ ull pack2(float lo, float hi) {
    ull r; asm("mov.b64 %0, {%1, %2};" : "=l"(r) : "f"(lo), "f"(hi)); return r;
}
__device__ __forceinline__ float2 unpack2(ull v) {
    float2 r; asm("mov.b64 {%0, %1}, %2;" : "=f"(r.x), "=f"(r.y) : "l"(v)); return r;
}
__device__ __forceinline__ void fma2(ull& d, ull a, ull b) {
    asm("fma.rn.f32x2 %0, %1, %2, %0;" : "+l"(d) : "l"(a), "l"(b));
}
__device__ __forceinline__ float unpack_sum(ull v) {
    float2 f = unpack2(v); return f.x + f.y;
}

__device__ __forceinline__ void cp_commit() { asm volatile("cp.async.commit_group;"); }
__device__ __forceinline__ void cp_wait0()  { asm volatile("cp.async.wait_group 0;"); }

// Copy one 128x64 f32 tile (row stride 64 in gmem) into the padded stage buffer.
// 4096 8-byte chunks; 256 threads x 16 iters; gmem side fully coalesced.
__device__ __forceinline__ void stage_load(const float* __restrict__ src_rows,
                                           float* dstbuf, int tid) {
    #pragma unroll
    for (int u = 0; u < 16; u++) {
        int e  = tid + u * NT;
        int r  = e >> 5;
        int c2 = (e & 31) * 2;
        unsigned dst = (unsigned)__cvta_generic_to_shared(dstbuf + r * STR + c2);
        const float* src = src_rows + (size_t)r * DH + c2;
        asm volatile("cp.async.ca.shared.global [%0], [%1], 8;" :: "r"(dst), "l"(src));
    }
    cp_commit();
}

// Shared memory layout (dynamic), total 93184 B -> 2 CTAs/SM:
//   [0,     2048)   q_t2  : ull[32][8]     q tile, k-pairs x i (transposed)
//   [2048, 34816)   bias  : f32[8][1024]   phases 1-2; scat2 ull[1024][4] phase 4+
//   [34816,51200)   sc    : f32[8][512]    scores (ph 2-4); red f32[8][32][16] ph5
//   [51200,59392)   idxs  : u16[8][512]    phases 2,4
//   [59392,93184)   stg   : 128 x STR f32 single stage buffer (ph 1-2);
//                           sc2 ull[512][4] (16KB) from phase 3 on
#define OFF_BIAS 2048
#define OFF_SC   (OFF_BIAS + 32768)
#define OFF_IDX  (OFF_SC + 16384)
#define OFF_STG  (OFF_IDX + 8192)
#define SMEM_BYTES (OFF_STG + STG_F * 4)

__global__ void __launch_bounds__(NT, 2)
ra_attn_kernel(const float* __restrict__ q,  const float* __restrict__ k,
               const float* __restrict__ v,  const float* __restrict__ rk,
               const float* __restrict__ rv, const void* __restrict__ pm_raw,
               const int* __restrict__ mask,
               float* attn_out, float* p_out)
{
    if (attn_out == nullptr) attn_out = g_scratch;
    if (p_out    == nullptr) p_out    = g_scratch;

    extern __shared__ char smem_raw[];
    ull*            q_t2  = (ull*)smem_raw;
    float*          bias  = (float*)(smem_raw + OFF_BIAS);
    float*          scat2 = bias;                               // ull[1024][4] view
    float*          sc    = (float*)(smem_raw + OFF_SC);
    float*          red   = sc;                                 // ph5 reduction
    unsigned short* idxs  = (unsigned short*)(smem_raw + OFF_IDX);
    float*          stg   = (float*)(smem_raw + OFF_STG);
    float*          sc2   = stg;                                // ull[512][4] view

    const int bh     = blockIdx.x >> 6;          // 64 tiles per bh
    const int tile   = blockIdx.x & 63;
    const int b      = bh >> 3;
    const int i_base = tile * TQ;
    const int tid    = threadIdx.x;

    const float* qg  = q  + (size_t)bh * LQ * DH;
    const float* kg  = k  + (size_t)bh * LQ * DH;
    const float* vg  = v  + (size_t)bh * LQ * DH;
    const float* rkg = rk + (size_t)bh * PN * DH;
    const float* rvg = rv + (size_t)bh * PN * DH;
    const int*   mg  = mask + (size_t)b * LQ * LQ;

    // ---- path_map dtype sniff (int64 vs int32) ----------------------------
    const long long* pm64 = (const long long*)pm_raw;
    const int*       pm32 = (const int*)pm_raw;
    bool is64 = true;
    #pragma unroll
    for (int t = 0; t < 8; t++) {
        long long vv = pm64[t];
        if (vv < 0 || vv > PN) is64 = false;
    }
    const size_t pm_base = (size_t)b * LQ * LQ;

    // ---- phase 0: load q tile, transposed into k-pairs --------------------
    {
        int i = tid >> 5, k2 = tid & 31;         // 256 = 8*32 exactly
        float2 qv = *(const float2*)(qg + (size_t)(i_base + i) * DH + k2 * 2);
        q_t2[k2 * TQ + i] = pack2(qv.x, qv.y);
    }

    // thread -> (row-in-stage, i-quad) mapping for phases 1 and 2
    const int p_loc = tid & 127;                 // 128 staged rows
    const int i4    = (tid >> 7) * 4;            // 0 or 4
    __syncthreads();

    // ---- phase 1: bias[8][1024] = q_tile @ r_k^T (8 single-buffered stages)
    stage_load(rkg, stg, tid);
    #pragma unroll 1
    for (int s = 0; s < 8; s++) {
        cp_wait0();
        __syncthreads();

        const float* B = stg + p_loc * STR;
        ull acc[4];
        acc[0] = acc[1] = acc[2] = acc[3] = 0ULL;

        #pragma unroll 8
        for (int k2 = 0; k2 < 32; k2++) {
            ulonglong2 q01 = *(const ulonglong2*)(q_t2 + k2 * TQ + i4);      // broadcast
            ulonglong2 q23 = *(const ulonglong2*)(q_t2 + k2 * TQ + i4 + 2);  // broadcast
            ull rkv = *(const ull*)(B + k2 * 2);
            fma2(acc[0], rkv, q01.x); fma2(acc[1], rkv, q01.y);
            fma2(acc[2], rkv, q23.x); fma2(acc[3], rkv, q23.y);
        }
        __syncthreads();                         // all reads of stg complete
        if (s < 7) stage_load(rkg + (size_t)(s + 1) * SROWS * DH, stg, tid);

        int p = s * SROWS + p_loc;
        #pragma unroll
        for (int ii = 0; ii < 4; ii++) bias[(i4 + ii) * PN + p] = unpack_sum(acc[ii]);
    }
    __syncthreads();   // bias complete before phase 2 gathers; stg reads done

    // ---- phase 2: scores[8][512] = q@K^T + gather(bias), scale, mask ------
    stage_load(kg, stg, tid);
    #pragma unroll 1
    for (int s = 0; s < 4; s++) {
        // prefetch path indices + mask for this stage (overlaps the cp wait)
        int j = s * SROWS + p_loc;
        int idxr[4], mr[4];
        #pragma unroll
        for (int ii = 0; ii < 4; ii++) {
            int    ig  = i_base + i4 + ii;
            size_t ofs = pm_base + (size_t)ig * LQ + j;
            idxr[ii] = is64 ? (int)pm64[ofs] : pm32[ofs];
            mr[ii]   = mg[(size_t)ig * LQ + j];
        }

        cp_wait0();
        __syncthreads();

        const float* B = stg + p_loc * STR;
        ull acc[4];
        acc[0] = acc[1] = acc[2] = acc[3] = 0ULL;

        #pragma unroll 8
        for (int k2 = 0; k2 < 32; k2++) {
            ulonglong2 q01 = *(const ulonglong2*)(q_t2 + k2 * TQ + i4);
            ulonglong2 q23 = *(const ulonglong2*)(q_t2 + k2 * TQ + i4 + 2);
            ull kv = *(const ull*)(B + k2 * 2);
            fma2(acc[0], kv, q01.x); fma2(acc[1], kv, q01.y);
            fma2(acc[2], kv, q23.x); fma2(acc[3], kv, q23.y);
        }
        __syncthreads();
        if (s < 3) stage_load(kg + (size_t)(s + 1) * SROWS * DH, stg, tid);

        #pragma unroll
        for (int ii = 0; ii < 4; ii++) {
            int   i   = i4 + ii;
            float sv  = unpack_sum(acc[ii]);
            int   idx = idxr[ii];
            if (idx < PN) sv += bias[i * PN + idx];
            sv *= 0.125f;                        // 1/sqrt(64*SQRT_NORM)
            if (mr[ii] == 0) sv = -1e9f;
            sc[i * LQ + j]   = sv;
            idxs[i * LQ + j] = (unsigned short)idx;
        }
    }
    __syncthreads();   // sc/idxs visible; stg dead -> sc2 region free

    // ---- phase 3: row softmax; write p_attn + packed sc2[j][i/2] ----------
    {
        int warp = tid >> 5, lane = tid & 31;
        float* row = sc + warp * LQ;
        float  m   = -1e30f;
        #pragma unroll 4
        for (int jj = lane; jj < LQ; jj += 32) m = fmaxf(m, row[jj]);
        #pragma unroll
        for (int o = 16; o; o >>= 1) m = fmaxf(m, __shfl_xor_sync(0xffffffffu, m, o));
        float ssum = 0.f;
        #pragma unroll 4
        for (int jj = lane; jj < LQ; jj += 32) {
            float e = __expf(row[jj] - m);
            row[jj] = e;
            ssum += e;
        }
        #pragma unroll
        for (int o = 16; o; o >>= 1) ssum += __shfl_xor_sync(0xffffffffu, ssum, o);
        float inv = 1.0f / ssum;
        float* pg = p_out + ((size_t)bh * LQ + (i_base + warp)) * LQ;
        #pragma unroll 4
        for (int jj = lane; jj < LQ; jj += 32) {
            float pv = row[jj] * inv;
            row[jj]  = pv;
            pg[jj]   = pv;
            sc2[jj * 8 + warp] = pv;             // packed [j][i] layout for ph5
        }
    }
    __syncthreads();

    // ---- phase 4: scat2 ull[1024][4] (reuse bias smem), packed [p][i/2] ---
    #pragma unroll 8
    for (int e = tid; e < PN * TQ; e += NT) scat2[e] = 0.f;
    __syncthreads();
    {
        int i  = tid & 7;
        int j0 = (tid >> 3) * 16;                // 32 chunks of 16 j per row
        const unsigned short* irow = idxs + i * LQ;
        const float*          prow = sc + i * LQ;
        #pragma unroll 4
        for (int jj = 0; jj < 16; jj++) {
            int j   = j0 + jj;
            int idx = irow[j];
            if (idx < PN) atomicAdd(&scat2[idx * 8 + i], prow[j]);
        }
    }
    __syncthreads();   // scat2 ready; sc (row) dead after this -> red usable

    // ---- phase 5: out[8][64] = p@V + scat@r_v -----------------------------
    // One warp per 2 rows/iter: lanes 0-15 -> row j, 16-31 -> row j+1.
    // Each lane: 4 d-columns x 8 i (as 4 f32x2 i-pairs) register accumulators.
    {
        int warp = tid >> 5, lane = tid & 31;
        int jh   = lane >> 4;                    // 0 or 1
        int d0   = (lane & 15) * 4;
        ull acc[4][4];                           // [i-pair][d]
        #pragma unroll
        for (int ip = 0; ip < 4; ip++)
            #pragma unroll
            for (int dd = 0; dd < 4; dd++) acc[ip][dd] = 0ULL;

        // V part: rows [warp*64, warp*64+64)
        #pragma unroll 4
        for (int it = 0; it < 32; it++) {
            int j = warp * 64 + it * 2 + jh;
            float4 vv = *(const float4*)(vg + (size_t)j * DH + d0);
            ull vd0 = pack2(vv.x, vv.x), vd1 = pack2(vv.y, vv.y);
            ull vd2 = pack2(vv.z, vv.z), vd3 = pack2(vv.w, vv.w);
            ulonglong2 w01 = *(const ulonglong2*)(sc2 + (size_t)j * 8);
            ulonglong2 w23 = *(const ulonglong2*)(sc2 + (size_t)j * 8 + 4);
            fma2(acc[0][0], w01.x, vd0); fma2(acc[0][1], w01.x, vd1);
            fma2(acc[0][2], w01.x, vd2); fma2(acc[0][3], w01.x, vd3);
            fma2(acc[1][0], w01.y, vd0); fma2(acc[1][1], w01.y, vd1);
            fma2(acc[1][2], w01.y, vd2); fma2(acc[1][3], w01.y, vd3);
            fma2(acc[2][0], w23.x, vd0); fma2(acc[2][1], w23.x, vd1);
            fma2(acc[2][2], w23.x, vd2); fma2(acc[2][3], w23.x, vd3);
            fma2(acc[3][0], w23.y, vd0); fma2(acc[3][1], w23.y, vd1);
            fma2(acc[3][2], w23.y, vd2); fma2(acc[3][3], w23.y, vd3);
        }
        // r_v part: rows [warp*128, warp*128+128)
        #pragma unroll 4
        for (int it = 0; it < 64; it++) {
            int j = warp * 128 + it * 2 + jh;
            float4 vv = *(const float4*)(rvg + (size_t)j * DH + d0);
            ull vd0 = pack2(vv.x, vv.x), vd1 = pack2(vv.y, vv.y);
            ull vd2 = pack2(vv.z, vv.z), vd3 = pack2(vv.w, vv.w);
            ulonglong2 w01 = *(const ulonglong2*)(scat2 + (size_t)j * 8);
            ulonglong2 w23 = *(const ulonglong2*)(scat2 + (size_t)j * 8 + 4);
            fma2(acc[0][0], w01.x, vd0); fma2(acc[0][1], w01.x, vd1);
            fma2(acc[0][2], w01.x, vd2); fma2(acc[0][3], w01.x, vd3);
            fma2(acc[1][0], w01.y, vd0); fma2(acc[1][1], w01.y, vd1);
            fma2(acc[1][2], w01.y, vd2); fma2(acc[1][3], w01.y, vd3);
            fma2(acc[2][0], w23.x, vd0); fma2(acc[2][1], w23.x, vd1);
            fma2(acc[2][2], w23.x, vd2); fma2(acc[2][3], w23.x, vd3);
            fma2(acc[3][0], w23.y, vd0); fma2(acc[3][1], w23.y, vd1);
            fma2(acc[3][2], w23.y, vd2); fma2(acc[3][3], w23.y, vd3);
        }

        // fold the two j-halves (lanes l and l+16 hold the same (i,d))
        // then lanes 0-15 write warp partials: red[warp][c=i*4+dd][lane&15]
        #pragma unroll
        for (int ip = 0; ip < 4; ip++) {
            #pragma unroll
            for (int dd = 0; dd < 4; dd++) {
                float2 f = unpack2(acc[ip][dd]);
                float lo = f.x + __shfl_xor_sync(0xffffffffu, f.x, 16);
                float hi = f.y + __shfl_xor_sync(0xffffffffu, f.y, 16);
                if (lane < 16) {
                    red[warp * 512 + ((2 * ip + 0) * 4 + dd) * 16 + lane] = lo;
                    red[warp * 512 + ((2 * ip + 1) * 4 + dd) * 16 + lane] = hi;
                }
            }
        }
    }
    __syncthreads();
    // final reduce over 8 warps; 256 threads x 2 outputs (512 = 8i x 64d)
    {
        #pragma unroll
        for (int h = 0; h < 2; h++) {
            int o = tid + h * 256;
            int i = o >> 6, d = o & 63;
            int c = i * 4 + (d & 3);
            int l = d >> 2;
            float s = 0.f;
            #pragma unroll
            for (int w = 0; w < 8; w++) s += red[w * 512 + c * 16 + l];
            attn_out[((size_t)bh * LQ + i_base + i) * DH + d] = s;
        }
    }
}

extern "C" void kernel_launch(void* const* d_in, const int* in_sizes, int n_in,
                              void* d_out, int out_size) {
    const float* q    = (const float*)d_in[0];
    const float* kk   = (const float*)d_in[1];
    const float* v    = (const float*)d_in[2];
    const float* rk   = (const float*)d_in[3];
    const float* rv   = (const float*)d_in[4];
    const void*  pm   = d_in[5];
    const int*   mask = (const int*)d_in[6];

    const long long ATT = (long long)BSZ * NH * LQ * DH;  //  2,097,152
    const long long PAT = (long long)BSZ * NH * LQ * LQ;  // 16,777,216

    float* out = (float*)d_out;
    float* attn_out;
    float* p_out;
    if ((long long)out_size >= ATT + PAT) {        // tuple concat: (attn_sum, p_attn)
        attn_out = out;
        p_out    = out + ATT;
    } else if ((long long)out_size == PAT) {       // p_attn only
        attn_out = nullptr;
        p_out    = out;
    } else {                                       // attn_sum only
        attn_out = out;
        p_out    = nullptr;
    }

    cudaFuncSetAttribute(ra_attn_kernel,
                         cudaFuncAttributeMaxDynamicSharedMemorySize, SMEM_BYTES);
    ra_attn_kernel<<<BSZ * NH * NTILE, NT, SMEM_BYTES>>>(
        q, kk, v, rk, rv, pm, mask, attn_out, p_out);
}

// round 16
// speedup vs baseline: 1.6693x; 1.0245x over previous
#include <cuda_runtime.h>
#include <cuda_bf16.h>

// ============================================================================
// RelationAwareAttention — GB300 sm_103a
//
// bs=8, h=8, L=512, d=64, P=1024.
//   bias[i][j]   = q_i . r_k[path_map[i,j]]            -> gather from dense q@r_k^T
//   out_rv[i][:] = sum_j p[i][j] * r_v[path_map[i,j]]  -> smem scatter + dense GEMM
//
// R15 measured L1=80.5% binding at 623us. This version: TQ=16, 512 threads,
// 256-row single-buffered stages, 1 CTA/SM (16 warps/SM unchanged):
//  * GEMM 8-i-deep: 6 wf per 8 fma2 (was 4 per 4)    -> -25% GEMM wf
//  * r_k/K staged once per 16 queries                 -> cp.async wf halved
//  * swizzled sc->sc2 transpose (4-wf-floor STS.128)  -> kills 16-way stores
//  * phase 5 identical per-thread shape (fma-bound part unchanged)
// ============================================================================

#define BSZ   8
#define NH    8
#define LQ    512
#define DH    64
#define PN    1024
#define TQ    16
#define NT    512
#define NTILE (LQ / TQ)          // 32 tiles per (b,h)

#define SROWS 256                // staged rows per (single) buffer
#define STR   66                 // padded floats per staged row
#define STG_F (SROWS * STR)      // 16896 floats = 67584 B

typedef unsigned long long ull;

static __device__ float g_scratch[BSZ * NH * LQ * LQ]; // fallback output buffer

__device__ __forceinline__ ull pack2(float lo, float hi) {
    ull r; asm("mov.b64 %0, {%1, %2};" : "=l"(r) : "f"(lo), "f"(hi)); return r;
}
__device__ __forceinline__ float2 unpack2(ull v) {
    float2 r; asm("mov.b64 {%0, %1}, %2;" : "=f"(r.x), "=f"(r.y) : "l"(v)); return r;
}
__device__ __forceinline__ void fma2(ull& d, ull a, ull b) {
    asm("fma.rn.f32x2 %0, %1, %2, %0;" : "+l"(d) : "l"(a), "l"(b));
}
__device__ __forceinline__ float unpack_sum(ull v) {
    float2 f = unpack2(v); return f.x + f.y;
}

__device__ __forceinline__ void cp_commit() { asm volatile("cp.async.commit_group;"); }
__device__ __forceinline__ void cp_wait0()  { asm volatile("cp.async.wait_group 0;"); }

// Copy one 256x64 f32 tile (row stride 64 in gmem) into the padded stage buffer.
// 8192 8-byte chunks; 512 threads x 16 iters; gmem side fully coalesced.
__device__ __forceinline__ void stage_load(const float* __restrict__ src_rows,
                                           float* dstbuf, int tid) {
    #pragma unroll
    for (int u = 0; u < 16; u++) {
        int e  = tid + u * NT;
        int r  = e >> 5;
        int c2 = (e & 31) * 2;
        unsigned dst = (unsigned)__cvta_generic_to_shared(dstbuf + r * STR + c2);
        const float* src = src_rows + (size_t)r * DH + c2;
        asm volatile("cp.async.ca.shared.global [%0], [%1], 8;" :: "r"(dst), "l"(src));
    }
    cp_commit();
}

// Shared memory layout (dynamic), total 186368 B (182 KB) -> 1 CTA/SM, 16 warps:
//   [0,      4096)   q_t2  : ull[32][16]    q tile, k-pairs x i (transposed)
//   [4096,  69632)   bias  : f32[16][1024]  ph 1-2; scat2 f32[1024][16] ph 4+
//   [69632, 102400)  sc    : f32[16][512]   scores (ph 2-4); red f32[16][512] ph5
//   [102400,118784)  idxs  : u16[16][512]   phases 2,4
//   [118784,186368)  stg   : 256 x STR f32 single stage buffer (ph 1-2);
//                            sc2 f32[512][16] swizzled (32KB) from transpose on
#define OFF_BIAS 4096
#define OFF_SC   (OFF_BIAS + 65536)
#define OFF_IDX  (OFF_SC + 32768)
#define OFF_STG  (OFF_IDX + 16384)
#define SMEM_BYTES (OFF_STG + STG_F * 4)

__global__ void __launch_bounds__(NT, 1)
ra_attn_kernel(const float* __restrict__ q,  const float* __restrict__ k,
               const float* __restrict__ v,  const float* __restrict__ rk,
               const float* __restrict__ rv, const void* __restrict__ pm_raw,
               const int* __restrict__ mask,
               float* attn_out, float* p_out)
{
    if (attn_out == nullptr) attn_out = g_scratch;
    if (p_out    == nullptr) p_out    = g_scratch;

    extern __shared__ char smem_raw[];
    ull*            q_t2  = (ull*)smem_raw;
    float*          bias  = (float*)(smem_raw + OFF_BIAS);
    float*          scat2 = bias;                               // f32[1024][16]
    float*          sc    = (float*)(smem_raw + OFF_SC);
    float*          red   = sc;                                 // ph5 reduction
    unsigned short* idxs  = (unsigned short*)(smem_raw + OFF_IDX);
    float*          stg   = (float*)(smem_raw + OFF_STG);
    float*          sc2   = stg;                                // f32[512][16] swizzled

    const int bh     = blockIdx.x >> 5;          // 32 tiles per bh
    const int tile   = blockIdx.x & 31;
    const int b      = bh >> 3;
    const int i_base = tile * TQ;
    const int tid    = threadIdx.x;

    const float* qg  = q  + (size_t)bh * LQ * DH;
    const float* kg  = k  + (size_t)bh * LQ * DH;
    const float* vg  = v  + (size_t)bh * LQ * DH;
    const float* rkg = rk + (size_t)bh * PN * DH;
    const float* rvg = rv + (size_t)bh * PN * DH;
    const int*   mg  = mask + (size_t)b * LQ * LQ;

    // ---- path_map dtype sniff (int64 vs int32) ----------------------------
    const long long* pm64 = (const long long*)pm_raw;
    const int*       pm32 = (const int*)pm_raw;
    bool is64 = true;
    #pragma unroll
    for (int t = 0; t < 8; t++) {
        long long vv = pm64[t];
        if (vv < 0 || vv > PN) is64 = false;
    }
    const size_t pm_base = (size_t)b * LQ * LQ;

    // ---- phase 0: load q tile, transposed into k-pairs --------------------
    {
        int i = tid >> 5, k2 = tid & 31;         // 512 = 16*32 exactly
        float2 qv = *(const float2*)(qg + (size_t)(i_base + i) * DH + k2 * 2);
        q_t2[k2 * TQ + i] = pack2(qv.x, qv.y);
    }

    // thread -> (row-in-stage, i-half) mapping for phases 1 and 2
    const int p_loc = tid & 255;                 // 256 staged rows
    const int ih    = (tid >> 8) * 8;            // 0 or 8
    __syncthreads();

    // ---- phase 1: bias[16][1024] = q_tile @ r_k^T (4 single-buffered stages)
    stage_load(rkg, stg, tid);
    #pragma unroll 1
    for (int s = 0; s < 4; s++) {
        cp_wait0();
        __syncthreads();

        const float* B = stg + p_loc * STR;
        ull acc[8];
        #pragma unroll
        for (int ii = 0; ii < 8; ii++) acc[ii] = 0ULL;

        #pragma unroll 8
        for (int k2 = 0; k2 < 32; k2++) {
            const ulonglong2* qp = (const ulonglong2*)(q_t2 + k2 * TQ + ih);
            ulonglong2 q01 = qp[0], q23 = qp[1], q45 = qp[2], q67 = qp[3];
            ull rkv = *(const ull*)(B + k2 * 2);
            fma2(acc[0], rkv, q01.x); fma2(acc[1], rkv, q01.y);
            fma2(acc[2], rkv, q23.x); fma2(acc[3], rkv, q23.y);
            fma2(acc[4], rkv, q45.x); fma2(acc[5], rkv, q45.y);
            fma2(acc[6], rkv, q67.x); fma2(acc[7], rkv, q67.y);
        }
        __syncthreads();                         // all reads of stg complete
        if (s < 3) stage_load(rkg + (size_t)(s + 1) * SROWS * DH, stg, tid);

        int p = s * SROWS + p_loc;
        #pragma unroll
        for (int ii = 0; ii < 8; ii++) bias[(ih + ii) * PN + p] = unpack_sum(acc[ii]);
    }
    __syncthreads();   // bias complete before phase 2 gathers; stg reads done

    // ---- phase 2: scores[16][512] = q@K^T + gather(bias), scale, mask -----
    stage_load(kg, stg, tid);
    #pragma unroll 1
    for (int s = 0; s < 2; s++) {
        int j = s * SROWS + p_loc;
        int idxr[8], mr[8];
        #pragma unroll
        for (int ii = 0; ii < 8; ii++) {
            int    ig  = i_base + ih + ii;
            size_t ofs = pm_base + (size_t)ig * LQ + j;
            idxr[ii] = is64 ? (int)pm64[ofs] : pm32[ofs];
            mr[ii]   = mg[(size_t)ig * LQ + j];
        }

        cp_wait0();
        __syncthreads();

        const float* B = stg + p_loc * STR;
        ull acc[8];
        #pragma unroll
        for (int ii = 0; ii < 8; ii++) acc[ii] = 0ULL;

        #pragma unroll 8
        for (int k2 = 0; k2 < 32; k2++) {
            const ulonglong2* qp = (const ulonglong2*)(q_t2 + k2 * TQ + ih);
            ulonglong2 q01 = qp[0], q23 = qp[1], q45 = qp[2], q67 = qp[3];
            ull kv = *(const ull*)(B + k2 * 2);
            fma2(acc[0], kv, q01.x); fma2(acc[1], kv, q01.y);
            fma2(acc[2], kv, q23.x); fma2(acc[3], kv, q23.y);
            fma2(acc[4], kv, q45.x); fma2(acc[5], kv, q45.y);
            fma2(acc[6], kv, q67.x); fma2(acc[7], kv, q67.y);
        }
        __syncthreads();
        if (s < 1) stage_load(kg + (size_t)SROWS * DH, stg, tid);

        #pragma unroll
        for (int ii = 0; ii < 8; ii++) {
            int   i   = ih + ii;
            float sv  = unpack_sum(acc[ii]);
            int   idx = idxr[ii];
            if (idx < PN) sv += bias[i * PN + idx];
            sv *= 0.125f;                        // 1/sqrt(64*SQRT_NORM)
            if (mr[ii] == 0) sv = -1e9f;
            sc[i * LQ + j]   = sv;
            idxs[i * LQ + j] = (unsigned short)idx;
        }
    }
    __syncthreads();   // sc/idxs visible; stg dead -> sc2 region free

    // ---- phase 3: row softmax (one warp per row, 16 warps); write p_attn --
    {
        int warp = tid >> 5, lane = tid & 31;
        float* row = sc + warp * LQ;
        float  m   = -1e30f;
        #pragma unroll 4
        for (int jj = lane; jj < LQ; jj += 32) m = fmaxf(m, row[jj]);
        #pragma unroll
        for (int o = 16; o; o >>= 1) m = fmaxf(m, __shfl_xor_sync(0xffffffffu, m, o));
        float ssum = 0.f;
        #pragma unroll 4
        for (int jj = lane; jj < LQ; jj += 32) {
            float e = __expf(row[jj] - m);
            row[jj] = e;
            ssum += e;
        }
        #pragma unroll
        for (int o = 16; o; o >>= 1) ssum += __shfl_xor_sync(0xffffffffu, ssum, o);
        float inv = 1.0f / ssum;
        float* pg = p_out + ((size_t)bh * LQ + (i_base + warp)) * LQ;
        #pragma unroll 4
        for (int jj = lane; jj < LQ; jj += 32) {
            float pv = row[jj] * inv;
            row[jj]  = pv;
            pg[jj]   = pv;
        }
    }
    __syncthreads();

    // ---- transpose sc -> sc2[j][16] (swizzled), and zero scat2 ------------
    // sc2 slot swizzle: 4-float group g of row j stored at slot g ^ ((j>>1)&3)
    // -> STS.128 at 4-wf floor, and 16B-aligned LDS.128 reads in phase 5.
    {
        int j = tid;                             // 0..511
        float va[16];
        #pragma unroll
        for (int i = 0; i < 16; i++) va[i] = sc[i * LQ + j];
        int sw = (j >> 1) & 3;
        #pragma unroll
        for (int g = 0; g < 4; g++) {
            float4 wv = make_float4(va[4*g], va[4*g+1], va[4*g+2], va[4*g+3]);
            *(float4*)(sc2 + j * 16 + ((g ^ sw) << 2)) = wv;
        }
        #pragma unroll
        for (int u = 0; u < 32; u++) scat2[tid + u * NT] = 0.f;   // 16384 floats
    }
    __syncthreads();

    // ---- phase 4: scatter p into scat2[p][16] -----------------------------
    {
        int i  = tid & 15;
        int j0 = (tid >> 4) * 16;                // 32 chunks of 16 j per row
        const unsigned short* irow = idxs + i * LQ;
        const float*          prow = sc + i * LQ;
        #pragma unroll 4
        for (int jj = 0; jj < 16; jj++) {
            int j   = j0 + jj;
            int idx = irow[j];
            if (idx < PN) atomicAdd(&scat2[idx * 16 + i], prow[j]);
        }
    }
    __syncthreads();   // scat2 ready; sc dead -> red usable

    // ---- phase 5: out[16][64] = p@V + scat@r_v ----------------------------
    // 16 warps = 8 row-groups x 2 i-halves. Lanes 0-15 row j, 16-31 row j+1;
    // each lane 4 d-cols x 8 i (4 f32x2 pairs) register accumulators.
    {
        int warp = tid >> 5, lane = tid & 31;
        int h    = warp & 1;                     // i-half: i = 8h..8h+7
        int grp  = warp >> 1;                    // 0..7
        int jh   = lane >> 4;
        int d0   = (lane & 15) * 4;
        ull acc[4][4];                           // [local i-pair][d]
        #pragma unroll
        for (int ip = 0; ip < 4; ip++)
            #pragma unroll
            for (int dd = 0; dd < 4; dd++) acc[ip][dd] = 0ULL;

        // V part: rows [grp*64, grp*64+64)
        #pragma unroll 4
        for (int it = 0; it < 32; it++) {
            int j = grp * 64 + it * 2 + jh;
            float4 vv = *(const float4*)(vg + (size_t)j * DH + d0);
            ull vd0 = pack2(vv.x, vv.x), vd1 = pack2(vv.y, vv.y);
            ull vd2 = pack2(vv.z, vv.z), vd3 = pack2(vv.w, vv.w);
            int sw = (j >> 1) & 3;
            ulonglong2 w01 = *(const ulonglong2*)(sc2 + j * 16 + (((2*h + 0) ^ sw) << 2));
            ulonglong2 w23 = *(const ulonglong2*)(sc2 + j * 16 + (((2*h + 1) ^ sw) << 2));
            fma2(acc[0][0], w01.x, vd0); fma2(acc[0][1], w01.x, vd1);
            fma2(acc[0][2], w01.x, vd2); fma2(acc[0][3], w01.x, vd3);
            fma2(acc[1][0], w01.y, vd0); fma2(acc[1][1], w01.y, vd1);
            fma2(acc[1][2], w01.y, vd2); fma2(acc[1][3], w01.y, vd3);
            fma2(acc[2][0], w23.x, vd0); fma2(acc[2][1], w23.x, vd1);
            fma2(acc[2][2], w23.x, vd2); fma2(acc[2][3], w23.x, vd3);
            fma2(acc[3][0], w23.y, vd0); fma2(acc[3][1], w23.y, vd1);
            fma2(acc[3][2], w23.y, vd2); fma2(acc[3][3], w23.y, vd3);
        }
        // r_v part: rows [grp*128, grp*128+128); scat2 is NOT swizzled
        #pragma unroll 4
        for (int it = 0; it < 64; it++) {
            int j = grp * 128 + it * 2 + jh;
            float4 vv = *(const float4*)(rvg + (size_t)j * DH + d0);
            ull vd0 = pack2(vv.x, vv.x), vd1 = pack2(vv.y, vv.y);
            ull vd2 = pack2(vv.z, vv.z), vd3 = pack2(vv.w, vv.w);
            ulonglong2 w01 = *(const ulonglong2*)(scat2 + (size_t)j * 16 + 8 * h);
            ulonglong2 w23 = *(const ulonglong2*)(scat2 + (size_t)j * 16 + 8 * h + 4);
            fma2(acc[0][0], w01.x, vd0); fma2(acc[0][1], w01.x, vd1);
            fma2(acc[0][2], w01.x, vd2); fma2(acc[0][3], w01.x, vd3);
            fma2(acc[1][0], w01.y, vd0); fma2(acc[1][1], w01.y, vd1);
            fma2(acc[1][2], w01.y, vd2); fma2(acc[1][3], w01.y, vd3);
            fma2(acc[2][0], w23.x, vd0); fma2(acc[2][1], w23.x, vd1);
            fma2(acc[2][2], w23.x, vd2); fma2(acc[2][3], w23.x, vd3);
            fma2(acc[3][0], w23.y, vd0); fma2(acc[3][1], w23.y, vd1);
            fma2(acc[3][2], w23.y, vd2); fma2(acc[3][3], w23.y, vd3);
        }

        // fold j-halves (lanes l, l+16 hold same (i,d)); lanes 0-15 write
        // red[warp*512 + (il*4+dd)*16 + lane], il = local i 0..7 = 2*ip+hh
        #pragma unroll
        for (int ip = 0; ip < 4; ip++) {
            #pragma unroll
            for (int dd = 0; dd < 4; dd++) {
                float2 f = unpack2(acc[ip][dd]);
                float lo = f.x + __shfl_xor_sync(0xffffffffu, f.x, 16);
                float hi = f.y + __shfl_xor_sync(0xffffffffu, f.y, 16);
                if (lane < 16) {
                    red[warp * 512 + ((2 * ip + 0) * 4 + dd) * 16 + lane] = lo;
                    red[warp * 512 + ((2 * ip + 1) * 4 + dd) * 16 + lane] = hi;
                }
            }
        }
    }
    __syncthreads();
    // final reduce over 8 row-groups; 512 threads x 2 outputs (1024 = 16i x 64d)
    {
        #pragma unroll
        for (int hh = 0; hh < 2; hh++) {
            int o = tid + hh * 512;
            int i = o >> 6, d = o & 63;
            int h  = i >> 3;
            int c  = (i & 7) * 4 + (d & 3);
            int l  = d >> 2;
            float s = 0.f;
            #pragma unroll
            for (int g = 0; g < 8; g++) s += red[(g * 2 + h) * 512 + c * 16 + l];
            attn_out[((size_t)bh * LQ + i_base + i) * DH + d] = s;
        }
    }
}

extern "C" void kernel_launch(void* const* d_in, const int* in_sizes, int n_in,
                              void* d_out, int out_size) {
    const float* q    = (const float*)d_in[0];
    const float* kk   = (const float*)d_in[1];
    const float* v    = (const float*)d_in[2];
    const float* rk   = (const float*)d_in[3];
    const float* rv   = (const float*)d_in[4];
    const void*  pm   = d_in[5];
    const int*   mask = (const int*)d_in[6];

    const long long ATT = (long long)BSZ * NH * LQ * DH;  //  2,097,152
    const long long PAT = (long long)BSZ * NH * LQ * LQ;  // 16,777,216

    float* out = (float*)d_out;
    float* attn_out;
    float* p_out;
    if ((long long)out_size >= ATT + PAT) {        // tuple concat: (attn_sum, p_attn)
        attn_out = out;
        p_out    = out + ATT;
    } else if ((long long)out_size == PAT) {       // p_attn only
        attn_out = nullptr;
        p_out    = out;
    } else {                                       // attn_sum only
        attn_out = out;
        p_out    = nullptr;
    }

    cudaFuncSetAttribute(ra_attn_kernel,
                         cudaFuncAttributeMaxDynamicSharedMemorySize, SMEM_BYTES);
    ra_attn_kernel<<<BSZ * NH * NTILE, NT, SMEM_BYTES>>>(
        q, kk, v, rk, rv, pm, mask, attn_out, p_out);
}